// round 13
// baseline (speedup 1.0000x reference)
#include <cuda_runtime.h>

#define BB 8
#define NPTS 2048
#define KNN 20
#define NG 8
#define EPSV 1e-5f

#define NEG_INF __int_as_float(0xff800000)
#define POS_INF __int_as_float(0x7f800000)

// ---------------- device scratch ----------------
__device__ float g_pd[BB][NPTS][NPTS];
__device__ float g_xx[BB][NPTS];
__device__ int   g_knn[BB][NPTS][KNN];
__device__ float g_res[BB][NPTS][256];
__device__ float g_U[BB][NPTS][128];
__device__ float g_V[BB][NPTS][128];
__device__ float g_maxv[BB][NPTS][128];
__device__ float g_minv[BB][NPTS][128];
__device__ float g_z[BB][256][NPTS];
__device__ float g_ssum[BB * NG];
__device__ float g_ssq[BB * NG];
__device__ float g_pool[BB][512];

// ---------------- xx = sum_c f^2 (+ zero the stage stats) ----------------
__global__ void xx_kernel(const float* __restrict__ f, long long bs, int rs, int C) {
    if (blockIdx.x == 0 && threadIdx.x < BB * NG) {
        g_ssum[threadIdx.x] = 0.f; g_ssq[threadIdx.x] = 0.f;
    }
    int row = blockIdx.x * 8 + (threadIdx.x >> 5);
    int lane = threadIdx.x & 31;
    int b = row / NPTS, n = row % NPTS;
    const float* p = f + (long long)b * bs + (long long)n * rs;
    float s = 0.f;
    for (int c = lane; c < C; c += 32) { float v = p[c]; s += v * v; }
#pragma unroll
    for (int o = 16; o; o >>= 1) s += __shfl_xor_sync(0xffffffffu, s, o);
    if (lane == 0) g_xx[b][n] = s;
}

// ---------------- pd (C=3 path): 64x64 tile ----------------
template <int C>
__global__ void pd_kernel(const float* __restrict__ f, long long bs, int rs, int bofs) {
    constexpr int KT = (C < 32) ? C : 32;
    __shared__ float sA[KT][68];
    __shared__ float sB[KT][68];
    int b = blockIdx.z + bofs;
    int n0 = blockIdx.y * 64, m0 = blockIdx.x * 64;
    int tx = threadIdx.x, ty = threadIdx.y;
    int tid = ty * 16 + tx;
    const float* fb = f + (long long)b * bs;
    float acc[4][4];
#pragma unroll
    for (int i = 0; i < 4; ++i)
#pragma unroll
        for (int j = 0; j < 4; ++j) acc[i][j] = 0.f;

    for (int k0 = 0; k0 < C; k0 += KT) {
        for (int t = tid; t < 64 * KT; t += 256) {
            int r = t / KT, c = t - r * KT;
            sA[c][r] = fb[(long long)(n0 + r) * rs + k0 + c];
            sB[c][r] = fb[(long long)(m0 + r) * rs + k0 + c];
        }
        __syncthreads();
#pragma unroll
        for (int c = 0; c < KT; ++c) {
            float4 a4 = *(const float4*)&sA[c][ty * 4];
            float4 b4 = *(const float4*)&sB[c][tx * 4];
            float a[4] = {a4.x, a4.y, a4.z, a4.w};
            float bv[4] = {b4.x, b4.y, b4.z, b4.w};
#pragma unroll
            for (int i = 0; i < 4; ++i)
#pragma unroll
                for (int j = 0; j < 4; ++j) acc[i][j] += a[i] * bv[j];
        }
        __syncthreads();
    }
    float xn[4], xm[4];
#pragma unroll
    for (int i = 0; i < 4; ++i) xn[i] = g_xx[b][n0 + ty * 4 + i];
#pragma unroll
    for (int j = 0; j < 4; ++j) xm[j] = g_xx[b][m0 + tx * 4 + j];
#pragma unroll
    for (int i = 0; i < 4; ++i) {
        float4 o4;
        o4.x = -(xn[i] - 2.f * acc[i][0] + xm[0]);
        o4.y = -(xn[i] - 2.f * acc[i][1] + xm[1]);
        o4.z = -(xn[i] - 2.f * acc[i][2] + xm[2]);
        o4.w = -(xn[i] - 2.f * acc[i][3] + xm[3]);
        *(float4*)&g_pd[b][n0 + ty * 4 + i][m0 + tx * 4] = o4;
    }
}

// ---------------- pd (C=64 path): 128x128 tile, 8x8 per thread ----------------
__global__ void __launch_bounds__(256) pd_kernel128(const float* __restrict__ f, long long bs, int rs, int bofs) {
    __shared__ float sA[32][132];
    __shared__ float sB[32][132];
    int b = blockIdx.z + bofs;
    int n0 = blockIdx.y * 128, m0 = blockIdx.x * 128;
    int tx = threadIdx.x, ty = threadIdx.y;
    int tid = ty * 16 + tx;
    const float* fb = f + (long long)b * bs;
    float acc[8][8];
#pragma unroll
    for (int i = 0; i < 8; ++i)
#pragma unroll
        for (int j = 0; j < 8; ++j) acc[i][j] = 0.f;

    for (int k0 = 0; k0 < 64; k0 += 32) {
        for (int t = tid; t < 128 * 32; t += 256) {
            int r = t >> 5, c = t & 31;
            sA[c][r] = fb[(long long)(n0 + r) * rs + k0 + c];
            sB[c][r] = fb[(long long)(m0 + r) * rs + k0 + c];
        }
        __syncthreads();
#pragma unroll
        for (int c = 0; c < 32; ++c) {
            float4 a0 = *(const float4*)&sA[c][ty * 8];
            float4 a1 = *(const float4*)&sA[c][ty * 8 + 4];
            float4 b0 = *(const float4*)&sB[c][tx * 8];
            float4 b1 = *(const float4*)&sB[c][tx * 8 + 4];
            float a[8] = {a0.x, a0.y, a0.z, a0.w, a1.x, a1.y, a1.z, a1.w};
            float bv[8] = {b0.x, b0.y, b0.z, b0.w, b1.x, b1.y, b1.z, b1.w};
#pragma unroll
            for (int i = 0; i < 8; ++i)
#pragma unroll
                for (int j = 0; j < 8; ++j) acc[i][j] += a[i] * bv[j];
        }
        __syncthreads();
    }
    float xn[8], xm[8];
#pragma unroll
    for (int i = 0; i < 8; ++i) xn[i] = g_xx[b][n0 + ty * 8 + i];
#pragma unroll
    for (int j = 0; j < 8; ++j) xm[j] = g_xx[b][m0 + tx * 8 + j];
#pragma unroll
    for (int i = 0; i < 8; ++i) {
        int n = n0 + ty * 8 + i;
        float4 o4;
        o4.x = -(xn[i] - 2.f * acc[i][0] + xm[0]);
        o4.y = -(xn[i] - 2.f * acc[i][1] + xm[1]);
        o4.z = -(xn[i] - 2.f * acc[i][2] + xm[2]);
        o4.w = -(xn[i] - 2.f * acc[i][3] + xm[3]);
        *(float4*)&g_pd[b][n][m0 + tx * 8] = o4;
        o4.x = -(xn[i] - 2.f * acc[i][4] + xm[4]);
        o4.y = -(xn[i] - 2.f * acc[i][5] + xm[5]);
        o4.z = -(xn[i] - 2.f * acc[i][6] + xm[6]);
        o4.w = -(xn[i] - 2.f * acc[i][7] + xm[7]);
        *(float4*)&g_pd[b][n][m0 + tx * 8 + 4] = o4;
    }
}

// ---------------- exact top-K per row: rank-20 threshold + distributed rank pass ----------------
__device__ __forceinline__ unsigned int fkey(float x) {
    unsigned int u = __float_as_uint(x);
    return (u & 0x80000000u) ? ~u : (u | 0x80000000u);
}

#define C2MAX 320
#define FASTCAP 512

__global__ void __launch_bounds__(256) topk_kernel(int bofs) {
    __shared__ unsigned long long skey[FASTCAP];
    __shared__ int srank[FASTCAP];
    __shared__ unsigned int whist[8][256];
    __shared__ unsigned int suff[256];
    __shared__ float candv[NPTS];
    __shared__ int   candi[NPTS];
    __shared__ float c2v[C2MAX];
    __shared__ int   c2i[C2MAX];
    __shared__ float sgmax[32];
    __shared__ float sT;
    __shared__ int   s_cand, s_out, s_c2;
    __shared__ int   s_bin, s_r, s_bcnt;

    int row = blockIdx.x;
    int b = bofs + (row >> 11), n = row & (NPTS - 1);
    int tid = threadIdx.x;
    int w = tid >> 5, lane = tid & 31;

    if (tid == 0) s_cand = 0;

    // load 8 contiguous elements per thread, keep in registers
    const float4* pr4 = (const float4*)&g_pd[b][n][0];
    float4 x0 = __ldcs(&pr4[tid * 2]);
    float4 x1 = __ldcs(&pr4[tid * 2 + 1]);
    float xv[8] = {x0.x, x0.y, x0.z, x0.w, x1.x, x1.y, x1.z, x1.w};

    // ---- 32 disjoint group maxima (8 lanes = 64 elems per group) ----
    float lm = xv[0];
#pragma unroll
    for (int q = 1; q < 8; ++q) lm = fmaxf(lm, xv[q]);
#pragma unroll
    for (int o = 1; o < 8; o <<= 1) lm = fmaxf(lm, __shfl_xor_sync(0xffffffffu, lm, o));
    if ((lane & 7) == 0) sgmax[w * 4 + (lane >> 3)] = lm;
    __syncthreads();

    // ---- T = 20th largest of the 32 group maxima (unique (value, lane) order) ----
    if (tid < 32) {
        float v = sgmax[tid];
        int cnt = 0;
#pragma unroll
        for (int j = 0; j < 32; ++j) {
            float vj = __shfl_sync(0xffffffffu, v, j);
            cnt += (vj > v) || (vj == v && j < tid);
        }
        if (cnt == KNN - 1) sT = v;
    }
    __syncthreads();
    float T = sT;

    // ---- compact survivors (x >= T) as packed u64 keys: (fkey << 32) | ~idx ----
#pragma unroll
    for (int q = 0; q < 8; ++q) {
        if (xv[q] >= T) {
            int pos = atomicAdd(&s_cand, 1);
            if (pos < FASTCAP)
                skey[pos] = ((unsigned long long)fkey(xv[q]) << 32)
                          | (unsigned int)(0xffffffffu - (unsigned int)(tid * 8 + q));
        }
    }
    __syncthreads();
    int c = s_cand;

    if (c <= FASTCAP) {
        // ---- distributed parallel rank pass: keys unique; exactly KNN ranks < KNN ----
        for (int p = tid; p < c; p += 256) srank[p] = 0;
        __syncthreads();
        if (c <= 128) {
            int nch = 256 / c;
            if (tid < nch * c) {
                int p = tid % c, ch = tid / c;
                unsigned long long mk = skey[p];
                int cnt = 0;
                for (int i = ch; i < c; i += nch) cnt += (skey[i] > mk);
                if (cnt) atomicAdd(&srank[p], cnt);
            }
        } else {
            for (int p = tid; p < c; p += 256) {
                unsigned long long mk = skey[p];
                int cnt = 0;
                for (int i = 0; i < c; ++i) cnt += (skey[i] > mk);
                srank[p] = cnt;
            }
        }
        __syncthreads();
        for (int p = tid; p < c; p += 256) {
            int r = srank[p];
            if (r < KNN)
                g_knn[b][n][r] = (int)(0xffffffffu - (unsigned int)(skey[p] & 0xffffffffu));
        }
        return;
    }

    // ---- fallback (tie storms only): exact 2-pass radix select from registers ----
#pragma unroll
    for (int i = 0; i < 8; ++i) whist[i][tid] = 0;
    if (tid == 0) { s_cand = 0; s_out = 0; s_c2 = 0; }
    __syncthreads();

    int bin[8];
#pragma unroll
    for (int q = 0; q < 8; ++q) {
        bin[q] = fkey(xv[q]) >> 24;
        atomicAdd(&whist[w][bin[q]], 1u);
    }
    __syncthreads();

    unsigned int h = 0;
#pragma unroll
    for (int i = 0; i < 8; ++i) h += whist[i][tid];
    suff[tid] = h;
    __syncthreads();
#pragma unroll
    for (int off = 1; off < 256; off <<= 1) {
        unsigned int v = suff[tid] + ((tid + off < 256) ? suff[tid + off] : 0u);
        __syncthreads();
        suff[tid] = v;
        __syncthreads();
    }
    unsigned int cgt = suff[tid] - h;
    if (cgt < KNN && cgt + h >= KNN) { s_bin = tid; s_r = KNN - (int)cgt; }
    __syncthreads();
    int binB = s_bin, r = s_r;

#pragma unroll
    for (int q = 0; q < 8; ++q) {
        int idx = tid * 8 + q;
        if (bin[q] > binB) {
            int p = atomicAdd(&s_out, 1);
            g_knn[b][n][p] = idx;
        } else if (bin[q] == binB) {
            int p = atomicAdd(&s_cand, 1);
            candv[p] = xv[q]; candi[p] = idx;
        }
    }
    __syncthreads();
    int cnt = s_cand;

    float* fv = candv; int* fi = candi;
    int fcnt = cnt, fr = r;

    if (cnt > 48) {
#pragma unroll
        for (int i = 0; i < 8; ++i) whist[i][tid] = 0;
        __syncthreads();
        for (int p = tid; p < cnt; p += 256) {
            int b2 = (fkey(candv[p]) >> 16) & 0xff;
            atomicAdd(&whist[w][b2], 1u);
        }
        __syncthreads();
        unsigned int h2 = 0;
#pragma unroll
        for (int i = 0; i < 8; ++i) h2 += whist[i][tid];
        suff[tid] = h2;
        __syncthreads();
#pragma unroll
        for (int off = 1; off < 256; off <<= 1) {
            unsigned int v = suff[tid] + ((tid + off < 256) ? suff[tid + off] : 0u);
            __syncthreads();
            suff[tid] = v;
            __syncthreads();
        }
        unsigned int cgt2 = suff[tid] - h2;
        if (cgt2 < (unsigned)r && cgt2 + h2 >= (unsigned)r) {
            s_bin = tid; s_r = r - (int)cgt2; s_bcnt = (int)h2;
        }
        __syncthreads();
        int binB2 = s_bin, r2 = s_r, bcnt = s_bcnt;

        if (bcnt <= C2MAX) {
            for (int p = tid; p < cnt; p += 256) {
                int b2 = (fkey(candv[p]) >> 16) & 0xff;
                if (b2 > binB2) {
                    int q = atomicAdd(&s_out, 1);
                    g_knn[b][n][q] = candi[p];
                } else if (b2 == binB2) {
                    int q = atomicAdd(&s_c2, 1);
                    c2v[q] = candv[p]; c2i[q] = candi[p];
                }
            }
            __syncthreads();
            fv = c2v; fi = c2i; fcnt = s_c2; fr = r2;
        }
    }

    if (w == 0) {
        int base = s_out;   // == KNN - fr
        for (int round = 0; round < fr; ++round) {
            unsigned long long best = 0ull; int bp = -1;
            for (int p = lane; p < fcnt; p += 32) {
                float v = fv[p];
                unsigned long long pk = ((unsigned long long)fkey(v) << 32)
                                      | (unsigned int)(0xffffffffu - (unsigned int)fi[p]);
                if (v != NEG_INF && pk > best) { best = pk; bp = p; }
            }
            unsigned long long wb = best;
#pragma unroll
            for (int o = 16; o; o >>= 1) {
                unsigned long long ov = __shfl_xor_sync(0xffffffffu, wb, o);
                if (ov > wb) wb = ov;
            }
            if (best == wb && bp >= 0) {
                fv[bp] = NEG_INF;
                g_knn[b][n][base + round] = (int)(0xffffffffu - (unsigned int)(wb & 0xffffffffu));
            }
            __syncwarp();
        }
    }
}

// ---------------- U = f*W1^T, V = f*(W2-W1)^T + b ----------------
template <int C>
__global__ void uv_gemm(const float* __restrict__ f, long long bs, int rs,
                        const float* __restrict__ w, const float* __restrict__ bias) {
    constexpr int KT = (C < 32) ? C : 32;
    __shared__ float sF[KT][68];
    __shared__ float sW1[KT][68];
    __shared__ float sDW[KT][68];
    int b = blockIdx.y;
    int n0 = blockIdx.x * 64;
    int o0 = blockIdx.z * 64;
    int tx = threadIdx.x, ty = threadIdx.y;
    int tid = ty * 16 + tx;
    const float* fb = f + (long long)b * bs;
    float au[4][4], av[4][4];
#pragma unroll
    for (int i = 0; i < 4; ++i)
#pragma unroll
        for (int j = 0; j < 4; ++j) { au[i][j] = 0.f; av[i][j] = 0.f; }

    for (int k0 = 0; k0 < C; k0 += KT) {
        for (int t = tid; t < 64 * KT; t += 256) {
            int r = t / KT, c = t - r * KT;
            sF[c][r] = fb[(long long)(n0 + r) * rs + k0 + c];
            float w1 = w[(o0 + r) * 2 * C + k0 + c];
            float w2 = w[(o0 + r) * 2 * C + C + k0 + c];
            sW1[c][r] = w1; sDW[c][r] = w2 - w1;
        }
        __syncthreads();
#pragma unroll
        for (int c = 0; c < KT; ++c) {
            float4 f4 = *(const float4*)&sF[c][ty * 4];
            float4 w4 = *(const float4*)&sW1[c][tx * 4];
            float4 d4 = *(const float4*)&sDW[c][tx * 4];
            float a[4] = {f4.x, f4.y, f4.z, f4.w};
            float wv[4] = {w4.x, w4.y, w4.z, w4.w};
            float dv[4] = {d4.x, d4.y, d4.z, d4.w};
#pragma unroll
            for (int i = 0; i < 4; ++i)
#pragma unroll
                for (int j = 0; j < 4; ++j) {
                    au[i][j] += a[i] * wv[j];
                    av[i][j] += a[i] * dv[j];
                }
        }
        __syncthreads();
    }
    float bb0 = bias[o0 + tx * 4 + 0];
    float bb1 = bias[o0 + tx * 4 + 1];
    float bb2 = bias[o0 + tx * 4 + 2];
    float bb3 = bias[o0 + tx * 4 + 3];
#pragma unroll
    for (int i = 0; i < 4; ++i) {
        int n = n0 + ty * 4 + i;
        float4 u4 = {au[i][0], au[i][1], au[i][2], au[i][3]};
        float4 v4 = {av[i][0] + bb0, av[i][1] + bb1, av[i][2] + bb2, av[i][3] + bb3};
        *(float4*)&g_U[b][n][o0 + tx * 4] = u4;
        *(float4*)&g_V[b][n][o0 + tx * 4] = v4;
    }
}

// ---------------- gather + k-max/min + GN stats ----------------
template <int O, int P>
__global__ void gather_reduce() {
    constexpr int PY = 256 / O;
    __shared__ int sidx[P][KNN];
    __shared__ float red[256];
    int o = threadIdx.x, py = threadIdx.y;
    int t = py * O + o;
    int b = blockIdx.y, n0 = blockIdx.x * P;
    for (int j = t; j < P * KNN; j += 256)
        sidx[j / KNN][j % KNN] = g_knn[b][n0 + j / KNN][j % KNN];
    __syncthreads();
    float ts1 = 0.f, ts2 = 0.f;
    for (int p = py; p < P; p += PY) {
        int n = n0 + p;
        float v = g_V[b][n][o];
        float mx = NEG_INF, mn = POS_INF;
#pragma unroll
        for (int k = 0; k < KNN; ++k) {
            float y = g_U[b][sidx[p][k]][o] + v;
            mx = fmaxf(mx, y); mn = fminf(mn, y);
            ts1 += y; ts2 += y * y;
        }
        g_maxv[b][n][o] = mx;
        g_minv[b][n][o] = mn;
    }
    red[t] = ts1; __syncthreads();
    if (t < NG) {
        float s = 0.f;
        for (int pp = 0; pp < PY; ++pp)
            for (int i = 0; i < O / NG; ++i) s += red[pp * O + t * (O / NG) + i];
        atomicAdd(&g_ssum[b * NG + t], s);
    }
    __syncthreads();
    red[t] = ts2; __syncthreads();
    if (t < NG) {
        float s = 0.f;
        for (int pp = 0; pp < PY; ++pp)
            for (int i = 0; i < O / NG; ++i) s += red[pp * O + t * (O / NG) + i];
        atomicAdd(&g_ssq[b * NG + t], s);
    }
}

// ---------------- GN + lrelu applied to k-extremum ----------------
template <int O>
__global__ void apply_kernel(const float* __restrict__ gamma, const float* __restrict__ beta, int col0) {
    int l = blockIdx.x * blockDim.x + threadIdx.x;
    int o = l % O;
    int n = (l / O) % NPTS;
    int b = l / (O * NPTS);
    int g = o / (O / NG);
    float cnt = (float)(O / NG) * NPTS * KNN;
    float mean = g_ssum[b * NG + g] / cnt;
    float var = fmaxf(g_ssq[b * NG + g] / cnt - mean * mean, 0.f);
    float inv = rsqrtf(var + EPSV);
    float s = gamma[o] * inv;
    float tt = beta[o] - mean * s;
    float sel = (s >= 0.f) ? g_maxv[b][n][o] : g_minv[b][n][o];
    float yv = s * sel + tt;
    g_res[b][n][col0 + o] = (yv >= 0.f) ? yv : 0.2f * yv;
}

// ---------------- w3 pointwise GEMM: 128x128 tile, 8x8 per thread ----------------
__global__ void __launch_bounds__(256) w3_gemm128(const float* __restrict__ w3, const float* __restrict__ b3) {
    __shared__ float sW[32][132];
    __shared__ float sR[32][132];
    int b = blockIdx.z;
    int o0 = blockIdx.y * 128, n0 = blockIdx.x * 128;
    int tx = threadIdx.x, ty = threadIdx.y;
    int tid = ty * 16 + tx;
    float acc[8][8];
#pragma unroll
    for (int i = 0; i < 8; ++i)
#pragma unroll
        for (int j = 0; j < 8; ++j) acc[i][j] = 0.f;

    for (int k0 = 0; k0 < 256; k0 += 32) {
        for (int t = tid; t < 128 * 32; t += 256) {
            int r = t >> 5, c = t & 31;
            sW[c][r] = w3[(o0 + r) * 256 + k0 + c];
            sR[c][r] = g_res[b][n0 + r][k0 + c];
        }
        __syncthreads();
#pragma unroll
        for (int c = 0; c < 32; ++c) {
            float4 a0 = *(const float4*)&sW[c][ty * 8];
            float4 a1 = *(const float4*)&sW[c][ty * 8 + 4];
            float4 b0 = *(const float4*)&sR[c][tx * 8];
            float4 b1 = *(const float4*)&sR[c][tx * 8 + 4];
            float a[8] = {a0.x, a0.y, a0.z, a0.w, a1.x, a1.y, a1.z, a1.w};
            float bv[8] = {b0.x, b0.y, b0.z, b0.w, b1.x, b1.y, b1.z, b1.w};
#pragma unroll
            for (int i = 0; i < 8; ++i)
#pragma unroll
                for (int j = 0; j < 8; ++j) acc[i][j] += a[i] * bv[j];
        }
        __syncthreads();
    }
#pragma unroll
    for (int i = 0; i < 8; ++i) {
        int o = o0 + ty * 8 + i;
        float bv = b3[o];
        float4 o4;
        o4.x = acc[i][0] + bv; o4.y = acc[i][1] + bv;
        o4.z = acc[i][2] + bv; o4.w = acc[i][3] + bv;
        *(float4*)&g_z[b][o][n0 + tx * 8] = o4;
        o4.x = acc[i][4] + bv; o4.y = acc[i][5] + bv;
        o4.z = acc[i][6] + bv; o4.w = acc[i][7] + bv;
        *(float4*)&g_z[b][o][n0 + tx * 8 + 4] = o4;
    }
}

// ---------------- stats of z per (b, group) ----------------
__global__ void stats3_kernel() {
    int b = blockIdx.x / NG, g = blockIdx.x % NG;
    int tid = threadIdx.x;
    float s1 = 0.f, s2 = 0.f;
    for (int i = tid; i < 32 * NPTS; i += 256) {
        int o = g * 32 + (i >> 11);
        int n = i & (NPTS - 1);
        float v = g_z[b][o][n];
        s1 += v; s2 += v * v;
    }
    __shared__ float r1[256], r2[256];
    r1[tid] = s1; r2[tid] = s2; __syncthreads();
    for (int st = 128; st; st >>= 1) {
        if (tid < st) { r1[tid] += r1[tid + st]; r2[tid] += r2[tid + st]; }
        __syncthreads();
    }
    if (tid == 0) { g_ssum[b * NG + g] = r1[0]; g_ssq[b * NG + g] = r2[0]; }
}

// ---------------- GN+lrelu+global max/mean pooling ----------------
__global__ void pool_kernel(const float* __restrict__ g3, const float* __restrict__ h3) {
    int b = blockIdx.x >> 8, o = blockIdx.x & 255;
    int g = o >> 5;
    float cnt = 32.f * NPTS;
    float mean = g_ssum[b * NG + g] / cnt;
    float var = fmaxf(g_ssq[b * NG + g] / cnt - mean * mean, 0.f);
    float inv = rsqrtf(var + EPSV);
    float s = g3[o] * inv;
    float tt = h3[o] - mean * s;
    int tid = threadIdx.x;
    float mx = NEG_INF, sum = 0.f;
    for (int n = tid; n < NPTS; n += 256) {
        float v = s * g_z[b][o][n] + tt;
        v = (v >= 0.f) ? v : 0.2f * v;
        mx = fmaxf(mx, v); sum += v;
    }
    __shared__ float rm[256], rs_[256];
    rm[tid] = mx; rs_[tid] = sum; __syncthreads();
    for (int st = 128; st; st >>= 1) {
        if (tid < st) { rm[tid] = fmaxf(rm[tid], rm[tid + st]); rs_[tid] += rs_[tid + st]; }
        __syncthreads();
    }
    if (tid == 0) { g_pool[b][o] = rm[0]; g_pool[b][256 + o] = rs_[0] / (float)NPTS; }
}

// ---------------- FC head ----------------
__global__ void head_kernel(const float* __restrict__ fw0, const float* __restrict__ fb0,
                            const float* __restrict__ fw1, const float* __restrict__ fb1,
                            const float* __restrict__ fw2, const float* __restrict__ fb2,
                            float* __restrict__ out) {
    __shared__ float sv[512];
    int b = blockIdx.x, t = threadIdx.x;
    sv[t] = g_pool[b][t];
    __syncthreads();
    float acc = fb0[t];
    {
        const float4* w4 = (const float4*)(fw0 + t * 512);
        const float4* v4 = (const float4*)sv;
        for (int c4 = 0; c4 < 128; ++c4) {
            float4 w = w4[c4]; float4 v = v4[c4];
            acc += w.x * v.x + w.y * v.y + w.z * v.z + w.w * v.w;
        }
    }
    acc = (acc >= 0.f) ? acc : 0.2f * acc;
    __syncthreads(); sv[t] = acc; __syncthreads();
    acc = fb1[t];
    {
        const float4* w4 = (const float4*)(fw1 + t * 512);
        const float4* v4 = (const float4*)sv;
        for (int c4 = 0; c4 < 128; ++c4) {
            float4 w = w4[c4]; float4 v = v4[c4];
            acc += w.x * v.x + w.y * v.y + w.z * v.z + w.w * v.w;
        }
    }
    acc = (acc >= 0.f) ? acc : 0.2f * acc;
    __syncthreads(); sv[t] = acc; __syncthreads();
    if (t < 256) {
        float a2 = fb2[t];
        const float4* w4 = (const float4*)(fw2 + t * 512);
        const float4* v4 = (const float4*)sv;
        for (int c4 = 0; c4 < 128; ++c4) {
            float4 w = w4[c4]; float4 v = v4[c4];
            a2 += w.x * v.x + w.y * v.y + w.z * v.z + w.w * v.w;
        }
        out[b * 256 + t] = a2;
    }
}

extern "C" void kernel_launch(void* const* d_in, const int* in_sizes, int n_in,
                              void* d_out, int out_size) {
    const float* x  = (const float*)d_in[0];
    const float* w0 = (const float*)d_in[1];
    const float* b0 = (const float*)d_in[2];
    const float* g0 = (const float*)d_in[3];
    const float* h0 = (const float*)d_in[4];
    const float* w1 = (const float*)d_in[5];
    const float* b1 = (const float*)d_in[6];
    const float* g1 = (const float*)d_in[7];
    const float* h1 = (const float*)d_in[8];
    const float* w2 = (const float*)d_in[9];
    const float* b2 = (const float*)d_in[10];
    const float* g2 = (const float*)d_in[11];
    const float* h2 = (const float*)d_in[12];
    const float* w3 = (const float*)d_in[13];
    const float* b3 = (const float*)d_in[14];
    const float* g3 = (const float*)d_in[15];
    const float* h3 = (const float*)d_in[16];
    const float* fw0 = (const float*)d_in[17];
    const float* fb0 = (const float*)d_in[18];
    const float* fw1 = (const float*)d_in[19];
    const float* fb1 = (const float*)d_in[20];
    const float* fw2 = (const float*)d_in[21];
    const float* fb2 = (const float*)d_in[22];
    float* out = (float*)d_out;

    float* resp = nullptr;
    cudaGetSymbolAddress((void**)&resp, g_res);

    dim3 blk16(16, 16);
    dim3 pd128grid(NPTS / 128, NPTS / 128, BB / 2);   // half-batch slices
    dim3 pd64grid(NPTS / 64, NPTS / 64, BB / 2);

    // ---------- stage 1: C=3 -> O=64 ----------
    // order: xx(0), uv(1), pd_h0(2), topk_h0(3)  -> ncu captures launch index 3 = topk
    {
        long long bs = (long long)NPTS * 3;
        xx_kernel<<<BB * NPTS / 8, 256>>>(x, bs, 3, 3);
        uv_gemm<3><<<dim3(NPTS / 64, BB, 1), blk16>>>(x, bs, 3, w0, b0);
        for (int h = 0; h < 2; ++h) {
            pd_kernel<3><<<pd64grid, blk16>>>(x, bs, 3, h * 4);
            topk_kernel<<<(BB / 2) * NPTS, 256>>>(h * 4);
        }
        gather_reduce<64, 16><<<dim3(NPTS / 16, BB), dim3(64, 4)>>>();
        apply_kernel<64><<<BB * NPTS * 64 / 256, 256>>>(g0, h0, 0);
    }
    // ---------- stage 2 ----------
    {
        long long bs = (long long)NPTS * 256;
        xx_kernel<<<BB * NPTS / 8, 256>>>(resp, bs, 256, 64);
        uv_gemm<64><<<dim3(NPTS / 64, BB, 1), blk16>>>(resp, bs, 256, w1, b1);
        for (int h = 0; h < 2; ++h) {
            pd_kernel128<<<pd128grid, blk16>>>(resp, bs, 256, h * 4);
            topk_kernel<<<(BB / 2) * NPTS, 256>>>(h * 4);
        }
        gather_reduce<64, 16><<<dim3(NPTS / 16, BB), dim3(64, 4)>>>();
        apply_kernel<64><<<BB * NPTS * 64 / 256, 256>>>(g1, h1, 64);
    }
    // ---------- stage 3 ----------
    {
        long long bs = (long long)NPTS * 256;
        const float* f = resp + 64;
        xx_kernel<<<BB * NPTS / 8, 256>>>(f, bs, 256, 64);
        uv_gemm<64><<<dim3(NPTS / 64, BB, 2), blk16>>>(f, bs, 256, w2, b2);
        for (int h = 0; h < 2; ++h) {
            pd_kernel128<<<pd128grid, blk16>>>(f, bs, 256, h * 4);
            topk_kernel<<<(BB / 2) * NPTS, 256>>>(h * 4);
        }
        gather_reduce<128, 8><<<dim3(NPTS / 8, BB), dim3(128, 2)>>>();
        apply_kernel<128><<<BB * NPTS * 128 / 256, 256>>>(g2, h2, 128);
    }
    // ---------- w3 pointwise + GN + pool + head ----------
    w3_gemm128<<<dim3(NPTS / 128, 256 / 128, BB), blk16>>>(w3, b3);
    stats3_kernel<<<BB * NG, 256>>>();
    pool_kernel<<<BB * 256, 256>>>(g3, h3);
    head_kernel<<<BB, 512>>>(fw0, fb0, fw1, fb1, fw2, fb2, out);
}

// round 15
// speedup vs baseline: 1.0368x; 1.0368x over previous
#include <cuda_runtime.h>

#define BB 8
#define NPTS 2048
#define KNN 20
#define NG 8
#define EPSV 1e-5f

#define NEG_INF __int_as_float(0xff800000)
#define POS_INF __int_as_float(0x7f800000)

// ---------------- device scratch ----------------
__device__ float g_pd[BB][NPTS][NPTS];
__device__ float g_xx[BB][NPTS];
__device__ int   g_knn[BB][NPTS][KNN];
__device__ float g_res[BB][NPTS][256];
__device__ float g_U[BB][NPTS][128];
__device__ float g_V[BB][NPTS][128];
__device__ float g_maxv[BB][NPTS][128];
__device__ float g_minv[BB][NPTS][128];
__device__ float g_z[BB][256][NPTS];
__device__ float g_ssum[BB * NG];
__device__ float g_ssq[BB * NG];
__device__ float g_pool[BB][512];

// ---------------- xx = sum_c f^2 (+ zero the stage stats) ----------------
__global__ void xx_kernel(const float* __restrict__ f, long long bs, int rs, int C) {
    if (blockIdx.x == 0 && threadIdx.x < BB * NG) {
        g_ssum[threadIdx.x] = 0.f; g_ssq[threadIdx.x] = 0.f;
    }
    int row = blockIdx.x * 8 + (threadIdx.x >> 5);
    int lane = threadIdx.x & 31;
    int b = row / NPTS, n = row % NPTS;
    const float* p = f + (long long)b * bs + (long long)n * rs;
    float s = 0.f;
    for (int c = lane; c < C; c += 32) { float v = p[c]; s += v * v; }
#pragma unroll
    for (int o = 16; o; o >>= 1) s += __shfl_xor_sync(0xffffffffu, s, o);
    if (lane == 0) g_xx[b][n] = s;
}

// ---------------- pd (C=3 path): 64x64 tile ----------------
template <int C>
__global__ void pd_kernel(const float* __restrict__ f, long long bs, int rs) {
    constexpr int KT = (C < 32) ? C : 32;
    __shared__ float sA[KT][68];
    __shared__ float sB[KT][68];
    int b = blockIdx.z;
    int n0 = blockIdx.y * 64, m0 = blockIdx.x * 64;
    int tx = threadIdx.x, ty = threadIdx.y;
    int tid = ty * 16 + tx;
    const float* fb = f + (long long)b * bs;
    float acc[4][4];
#pragma unroll
    for (int i = 0; i < 4; ++i)
#pragma unroll
        for (int j = 0; j < 4; ++j) acc[i][j] = 0.f;

    for (int k0 = 0; k0 < C; k0 += KT) {
        for (int t = tid; t < 64 * KT; t += 256) {
            int r = t / KT, c = t - r * KT;
            sA[c][r] = fb[(long long)(n0 + r) * rs + k0 + c];
            sB[c][r] = fb[(long long)(m0 + r) * rs + k0 + c];
        }
        __syncthreads();
#pragma unroll
        for (int c = 0; c < KT; ++c) {
            float4 a4 = *(const float4*)&sA[c][ty * 4];
            float4 b4 = *(const float4*)&sB[c][tx * 4];
            float a[4] = {a4.x, a4.y, a4.z, a4.w};
            float bv[4] = {b4.x, b4.y, b4.z, b4.w};
#pragma unroll
            for (int i = 0; i < 4; ++i)
#pragma unroll
                for (int j = 0; j < 4; ++j) acc[i][j] += a[i] * bv[j];
        }
        __syncthreads();
    }
    float xn[4], xm[4];
#pragma unroll
    for (int i = 0; i < 4; ++i) xn[i] = g_xx[b][n0 + ty * 4 + i];
#pragma unroll
    for (int j = 0; j < 4; ++j) xm[j] = g_xx[b][m0 + tx * 4 + j];
#pragma unroll
    for (int i = 0; i < 4; ++i) {
        float4 o4;
        o4.x = -(xn[i] - 2.f * acc[i][0] + xm[0]);
        o4.y = -(xn[i] - 2.f * acc[i][1] + xm[1]);
        o4.z = -(xn[i] - 2.f * acc[i][2] + xm[2]);
        o4.w = -(xn[i] - 2.f * acc[i][3] + xm[3]);
        __stcs((float4*)&g_pd[b][n0 + ty * 4 + i][m0 + tx * 4], o4);
    }
}

// ---------------- pd (C=64 path): 128x128 tile, 8x8 per thread ----------------
__global__ void __launch_bounds__(256) pd_kernel128(const float* __restrict__ f, long long bs, int rs) {
    __shared__ float sA[32][132];
    __shared__ float sB[32][132];
    int b = blockIdx.z;
    int n0 = blockIdx.y * 128, m0 = blockIdx.x * 128;
    int tx = threadIdx.x, ty = threadIdx.y;
    int tid = ty * 16 + tx;
    const float* fb = f + (long long)b * bs;
    float acc[8][8];
#pragma unroll
    for (int i = 0; i < 8; ++i)
#pragma unroll
        for (int j = 0; j < 8; ++j) acc[i][j] = 0.f;

    for (int k0 = 0; k0 < 64; k0 += 32) {
        for (int t = tid; t < 128 * 32; t += 256) {
            int r = t >> 5, c = t & 31;
            sA[c][r] = fb[(long long)(n0 + r) * rs + k0 + c];
            sB[c][r] = fb[(long long)(m0 + r) * rs + k0 + c];
        }
        __syncthreads();
#pragma unroll
        for (int c = 0; c < 32; ++c) {
            float4 a0 = *(const float4*)&sA[c][ty * 8];
            float4 a1 = *(const float4*)&sA[c][ty * 8 + 4];
            float4 b0 = *(const float4*)&sB[c][tx * 8];
            float4 b1 = *(const float4*)&sB[c][tx * 8 + 4];
            float a[8] = {a0.x, a0.y, a0.z, a0.w, a1.x, a1.y, a1.z, a1.w};
            float bv[8] = {b0.x, b0.y, b0.z, b0.w, b1.x, b1.y, b1.z, b1.w};
#pragma unroll
            for (int i = 0; i < 8; ++i)
#pragma unroll
                for (int j = 0; j < 8; ++j) acc[i][j] += a[i] * bv[j];
        }
        __syncthreads();
    }
    float xn[8], xm[8];
#pragma unroll
    for (int i = 0; i < 8; ++i) xn[i] = g_xx[b][n0 + ty * 8 + i];
#pragma unroll
    for (int j = 0; j < 8; ++j) xm[j] = g_xx[b][m0 + tx * 8 + j];
#pragma unroll
    for (int i = 0; i < 8; ++i) {
        int n = n0 + ty * 8 + i;
        float4 o4;
        o4.x = -(xn[i] - 2.f * acc[i][0] + xm[0]);
        o4.y = -(xn[i] - 2.f * acc[i][1] + xm[1]);
        o4.z = -(xn[i] - 2.f * acc[i][2] + xm[2]);
        o4.w = -(xn[i] - 2.f * acc[i][3] + xm[3]);
        __stcs((float4*)&g_pd[b][n][m0 + tx * 8], o4);
        o4.x = -(xn[i] - 2.f * acc[i][4] + xm[4]);
        o4.y = -(xn[i] - 2.f * acc[i][5] + xm[5]);
        o4.z = -(xn[i] - 2.f * acc[i][6] + xm[6]);
        o4.w = -(xn[i] - 2.f * acc[i][7] + xm[7]);
        __stcs((float4*)&g_pd[b][n][m0 + tx * 8 + 4], o4);
    }
}

// ---------------- exact top-K per row: rank-20 threshold + distributed rank pass ----------------
__device__ __forceinline__ unsigned int fkey(float x) {
    unsigned int u = __float_as_uint(x);
    return (u & 0x80000000u) ? ~u : (u | 0x80000000u);
}

#define C2MAX 320
#define FASTCAP 512

__global__ void __launch_bounds__(256) topk_kernel() {
    __shared__ unsigned long long skey[FASTCAP];
    __shared__ int srank[FASTCAP];
    __shared__ unsigned int whist[8][256];
    __shared__ unsigned int suff[256];
    __shared__ float candv[NPTS];
    __shared__ int   candi[NPTS];
    __shared__ float c2v[C2MAX];
    __shared__ int   c2i[C2MAX];
    __shared__ float sgmax[32];
    __shared__ float sT;
    __shared__ int   s_cand, s_out, s_c2;
    __shared__ int   s_bin, s_r, s_bcnt;

    int row = blockIdx.x;
    int b = row >> 11, n = row & (NPTS - 1);
    int tid = threadIdx.x;
    int w = tid >> 5, lane = tid & 31;

    if (tid == 0) s_cand = 0;
    // pre-zero rank array (used by the fast path) to save a barrier later
    srank[tid] = 0; srank[tid + 256] = 0;

    // load 8 contiguous elements per thread, keep in registers
    const float4* pr4 = (const float4*)&g_pd[b][n][0];
    float4 x0 = __ldcs(&pr4[tid * 2]);
    float4 x1 = __ldcs(&pr4[tid * 2 + 1]);
    float xv[8] = {x0.x, x0.y, x0.z, x0.w, x1.x, x1.y, x1.z, x1.w};

    // ---- per-thread max, then 32 disjoint group maxima (8 lanes = 64 elems each) ----
    float tmax = xv[0];
#pragma unroll
    for (int q = 1; q < 8; ++q) tmax = fmaxf(tmax, xv[q]);
    float lm = tmax;
#pragma unroll
    for (int o = 1; o < 8; o <<= 1) lm = fmaxf(lm, __shfl_xor_sync(0xffffffffu, lm, o));
    if ((lane & 7) == 0) sgmax[w * 4 + (lane >> 3)] = lm;
    __syncthreads();

    // ---- T = 20th largest of the 32 group maxima (unique (value, lane) order) ----
    // The 20 top maxima are DISTINCT elements >= T  =>  survivors >= KNN guaranteed.
    if (tid < 32) {
        float v = sgmax[tid];
        int cnt = 0;
#pragma unroll
        for (int j = 0; j < 32; ++j) {
            float vj = __shfl_sync(0xffffffffu, v, j);
            cnt += (vj > v) || (vj == v && j < tid);
        }
        if (cnt == KNN - 1) sT = v;
    }
    __syncthreads();
    float T = sT;

    // ---- compact survivors (x >= T) as packed u64 keys: (fkey << 32) | ~idx ----
    if (tmax >= T) {
        unsigned int ibase = 0xffffffffu - (unsigned int)(tid * 8);
#pragma unroll
        for (int q = 0; q < 8; ++q) {
            if (xv[q] >= T) {
                int pos = atomicAdd(&s_cand, 1);
                if (pos < FASTCAP)
                    skey[pos] = ((unsigned long long)fkey(xv[q]) << 32) | (ibase - q);
            }
        }
    }
    __syncthreads();
    int c = s_cand;

    if (c <= FASTCAP) {
        // ---- distributed parallel rank pass: keys unique; exactly KNN ranks < KNN ----
        if (c <= 128) {
            int nch = 256 / c;
            if (tid < nch * c) {
                int p = tid % c, ch = tid / c;
                unsigned long long mk = skey[p];
                int cnt = 0;
                for (int i = ch; i < c; i += nch) cnt += (skey[i] > mk);
                if (cnt) atomicAdd(&srank[p], cnt);
            }
        } else {
            for (int p = tid; p < c; p += 256) {
                unsigned long long mk = skey[p];
                int cnt = 0;
                for (int i = 0; i < c; ++i) cnt += (skey[i] > mk);
                srank[p] = cnt;
            }
        }
        __syncthreads();
        for (int p = tid; p < c; p += 256) {
            int r = srank[p];
            if (r < KNN)
                g_knn[b][n][r] = (int)(0xffffffffu - (unsigned int)(skey[p] & 0xffffffffu));
        }
        return;
    }

    // ---- fallback (tie storms only): exact 2-pass radix select from registers ----
#pragma unroll
    for (int i = 0; i < 8; ++i) whist[i][tid] = 0;
    if (tid == 0) { s_cand = 0; s_out = 0; s_c2 = 0; }
    __syncthreads();

    int bin[8];
#pragma unroll
    for (int q = 0; q < 8; ++q) {
        bin[q] = fkey(xv[q]) >> 24;
        atomicAdd(&whist[w][bin[q]], 1u);
    }
    __syncthreads();

    unsigned int h = 0;
#pragma unroll
    for (int i = 0; i < 8; ++i) h += whist[i][tid];
    suff[tid] = h;
    __syncthreads();
#pragma unroll
    for (int off = 1; off < 256; off <<= 1) {
        unsigned int v = suff[tid] + ((tid + off < 256) ? suff[tid + off] : 0u);
        __syncthreads();
        suff[tid] = v;
        __syncthreads();
    }
    unsigned int cgt = suff[tid] - h;
    if (cgt < KNN && cgt + h >= KNN) { s_bin = tid; s_r = KNN - (int)cgt; }
    __syncthreads();
    int binB = s_bin, r = s_r;

#pragma unroll
    for (int q = 0; q < 8; ++q) {
        int idx = tid * 8 + q;
        if (bin[q] > binB) {
            int p = atomicAdd(&s_out, 1);
            g_knn[b][n][p] = idx;
        } else if (bin[q] == binB) {
            int p = atomicAdd(&s_cand, 1);
            candv[p] = xv[q]; candi[p] = idx;
        }
    }
    __syncthreads();
    int cnt = s_cand;

    float* fv = candv; int* fi = candi;
    int fcnt = cnt, fr = r;

    if (cnt > 48) {
#pragma unroll
        for (int i = 0; i < 8; ++i) whist[i][tid] = 0;
        __syncthreads();
        for (int p = tid; p < cnt; p += 256) {
            int b2 = (fkey(candv[p]) >> 16) & 0xff;
            atomicAdd(&whist[w][b2], 1u);
        }
        __syncthreads();
        unsigned int h2 = 0;
#pragma unroll
        for (int i = 0; i < 8; ++i) h2 += whist[i][tid];
        suff[tid] = h2;
        __syncthreads();
#pragma unroll
        for (int off = 1; off < 256; off <<= 1) {
            unsigned int v = suff[tid] + ((tid + off < 256) ? suff[tid + off] : 0u);
            __syncthreads();
            suff[tid] = v;
            __syncthreads();
        }
        unsigned int cgt2 = suff[tid] - h2;
        if (cgt2 < (unsigned)r && cgt2 + h2 >= (unsigned)r) {
            s_bin = tid; s_r = r - (int)cgt2; s_bcnt = (int)h2;
        }
        __syncthreads();
        int binB2 = s_bin, r2 = s_r, bcnt = s_bcnt;

        if (bcnt <= C2MAX) {
            for (int p = tid; p < cnt; p += 256) {
                int b2 = (fkey(candv[p]) >> 16) & 0xff;
                if (b2 > binB2) {
                    int q = atomicAdd(&s_out, 1);
                    g_knn[b][n][q] = candi[p];
                } else if (b2 == binB2) {
                    int q = atomicAdd(&s_c2, 1);
                    c2v[q] = candv[p]; c2i[q] = candi[p];
                }
            }
            __syncthreads();
            fv = c2v; fi = c2i; fcnt = s_c2; fr = r2;
        }
    }

    if (w == 0) {
        int base = s_out;   // == KNN - fr
        for (int round = 0; round < fr; ++round) {
            unsigned long long best = 0ull; int bp = -1;
            for (int p = lane; p < fcnt; p += 32) {
                float v = fv[p];
                unsigned long long pk = ((unsigned long long)fkey(v) << 32)
                                      | (unsigned int)(0xffffffffu - (unsigned int)fi[p]);
                if (v != NEG_INF && pk > best) { best = pk; bp = p; }
            }
            unsigned long long wb = best;
#pragma unroll
            for (int o = 16; o; o >>= 1) {
                unsigned long long ov = __shfl_xor_sync(0xffffffffu, wb, o);
                if (ov > wb) wb = ov;
            }
            if (best == wb && bp >= 0) {
                fv[bp] = NEG_INF;
                g_knn[b][n][base + round] = (int)(0xffffffffu - (unsigned int)(wb & 0xffffffffu));
            }
            __syncwarp();
        }
    }
}

// ---------------- U = f*W1^T, V = f*(W2-W1)^T + b ----------------
template <int C>
__global__ void uv_gemm(const float* __restrict__ f, long long bs, int rs,
                        const float* __restrict__ w, const float* __restrict__ bias) {
    constexpr int KT = (C < 32) ? C : 32;
    __shared__ float sF[KT][68];
    __shared__ float sW1[KT][68];
    __shared__ float sDW[KT][68];
    int b = blockIdx.y;
    int n0 = blockIdx.x * 64;
    int o0 = blockIdx.z * 64;
    int tx = threadIdx.x, ty = threadIdx.y;
    int tid = ty * 16 + tx;
    const float* fb = f + (long long)b * bs;
    float au[4][4], av[4][4];
#pragma unroll
    for (int i = 0; i < 4; ++i)
#pragma unroll
        for (int j = 0; j < 4; ++j) { au[i][j] = 0.f; av[i][j] = 0.f; }

    for (int k0 = 0; k0 < C; k0 += KT) {
        for (int t = tid; t < 64 * KT; t += 256) {
            int r = t / KT, c = t - r * KT;
            sF[c][r] = fb[(long long)(n0 + r) * rs + k0 + c];
            float w1 = w[(o0 + r) * 2 * C + k0 + c];
            float w2 = w[(o0 + r) * 2 * C + C + k0 + c];
            sW1[c][r] = w1; sDW[c][r] = w2 - w1;
        }
        __syncthreads();
#pragma unroll
        for (int c = 0; c < KT; ++c) {
            float4 f4 = *(const float4*)&sF[c][ty * 4];
            float4 w4 = *(const float4*)&sW1[c][tx * 4];
            float4 d4 = *(const float4*)&sDW[c][tx * 4];
            float a[4] = {f4.x, f4.y, f4.z, f4.w};
            float wv[4] = {w4.x, w4.y, w4.z, w4.w};
            float dv[4] = {d4.x, d4.y, d4.z, d4.w};
#pragma unroll
            for (int i = 0; i < 4; ++i)
#pragma unroll
                for (int j = 0; j < 4; ++j) {
                    au[i][j] += a[i] * wv[j];
                    av[i][j] += a[i] * dv[j];
                }
        }
        __syncthreads();
    }
    float bb0 = bias[o0 + tx * 4 + 0];
    float bb1 = bias[o0 + tx * 4 + 1];
    float bb2 = bias[o0 + tx * 4 + 2];
    float bb3 = bias[o0 + tx * 4 + 3];
#pragma unroll
    for (int i = 0; i < 4; ++i) {
        int n = n0 + ty * 4 + i;
        float4 u4 = {au[i][0], au[i][1], au[i][2], au[i][3]};
        float4 v4 = {av[i][0] + bb0, av[i][1] + bb1, av[i][2] + bb2, av[i][3] + bb3};
        *(float4*)&g_U[b][n][o0 + tx * 4] = u4;
        *(float4*)&g_V[b][n][o0 + tx * 4] = v4;
    }
}

// ---------------- gather + k-max/min + GN stats ----------------
template <int O, int P>
__global__ void gather_reduce() {
    constexpr int PY = 256 / O;
    __shared__ int sidx[P][KNN];
    __shared__ float red[256];
    int o = threadIdx.x, py = threadIdx.y;
    int t = py * O + o;
    int b = blockIdx.y, n0 = blockIdx.x * P;
    for (int j = t; j < P * KNN; j += 256)
        sidx[j / KNN][j % KNN] = g_knn[b][n0 + j / KNN][j % KNN];
    __syncthreads();
    float ts1 = 0.f, ts2 = 0.f;
    for (int p = py; p < P; p += PY) {
        int n = n0 + p;
        float v = g_V[b][n][o];
        float mx = NEG_INF, mn = POS_INF;
#pragma unroll
        for (int k = 0; k < KNN; ++k) {
            float y = g_U[b][sidx[p][k]][o] + v;
            mx = fmaxf(mx, y); mn = fminf(mn, y);
            ts1 += y; ts2 += y * y;
        }
        g_maxv[b][n][o] = mx;
        g_minv[b][n][o] = mn;
    }
    red[t] = ts1; __syncthreads();
    if (t < NG) {
        float s = 0.f;
        for (int pp = 0; pp < PY; ++pp)
            for (int i = 0; i < O / NG; ++i) s += red[pp * O + t * (O / NG) + i];
        atomicAdd(&g_ssum[b * NG + t], s);
    }
    __syncthreads();
    red[t] = ts2; __syncthreads();
    if (t < NG) {
        float s = 0.f;
        for (int pp = 0; pp < PY; ++pp)
            for (int i = 0; i < O / NG; ++i) s += red[pp * O + t * (O / NG) + i];
        atomicAdd(&g_ssq[b * NG + t], s);
    }
}

// ---------------- GN + lrelu applied to k-extremum ----------------
template <int O>
__global__ void apply_kernel(const float* __restrict__ gamma, const float* __restrict__ beta, int col0) {
    int l = blockIdx.x * blockDim.x + threadIdx.x;
    int o = l % O;
    int n = (l / O) % NPTS;
    int b = l / (O * NPTS);
    int g = o / (O / NG);
    float cnt = (float)(O / NG) * NPTS * KNN;
    float mean = g_ssum[b * NG + g] / cnt;
    float var = fmaxf(g_ssq[b * NG + g] / cnt - mean * mean, 0.f);
    float inv = rsqrtf(var + EPSV);
    float s = gamma[o] * inv;
    float tt = beta[o] - mean * s;
    float sel = (s >= 0.f) ? g_maxv[b][n][o] : g_minv[b][n][o];
    float yv = s * sel + tt;
    g_res[b][n][col0 + o] = (yv >= 0.f) ? yv : 0.2f * yv;
}

// ---------------- w3 pointwise GEMM: 128x128 tile, 8x8 per thread ----------------
__global__ void __launch_bounds__(256) w3_gemm128(const float* __restrict__ w3, const float* __restrict__ b3) {
    __shared__ float sW[32][132];
    __shared__ float sR[32][132];
    int b = blockIdx.z;
    int o0 = blockIdx.y * 128, n0 = blockIdx.x * 128;
    int tx = threadIdx.x, ty = threadIdx.y;
    int tid = ty * 16 + tx;
    float acc[8][8];
#pragma unroll
    for (int i = 0; i < 8; ++i)
#pragma unroll
        for (int j = 0; j < 8; ++j) acc[i][j] = 0.f;

    for (int k0 = 0; k0 < 256; k0 += 32) {
        for (int t = tid; t < 128 * 32; t += 256) {
            int r = t >> 5, c = t & 31;
            sW[c][r] = w3[(o0 + r) * 256 + k0 + c];
            sR[c][r] = g_res[b][n0 + r][k0 + c];
        }
        __syncthreads();
#pragma unroll
        for (int c = 0; c < 32; ++c) {
            float4 a0 = *(const float4*)&sW[c][ty * 8];
            float4 a1 = *(const float4*)&sW[c][ty * 8 + 4];
            float4 b0 = *(const float4*)&sR[c][tx * 8];
            float4 b1 = *(const float4*)&sR[c][tx * 8 + 4];
            float a[8] = {a0.x, a0.y, a0.z, a0.w, a1.x, a1.y, a1.z, a1.w};
            float bv[8] = {b0.x, b0.y, b0.z, b0.w, b1.x, b1.y, b1.z, b1.w};
#pragma unroll
            for (int i = 0; i < 8; ++i)
#pragma unroll
                for (int j = 0; j < 8; ++j) acc[i][j] += a[i] * bv[j];
        }
        __syncthreads();
    }
#pragma unroll
    for (int i = 0; i < 8; ++i) {
        int o = o0 + ty * 8 + i;
        float bv = b3[o];
        float4 o4;
        o4.x = acc[i][0] + bv; o4.y = acc[i][1] + bv;
        o4.z = acc[i][2] + bv; o4.w = acc[i][3] + bv;
        *(float4*)&g_z[b][o][n0 + tx * 8] = o4;
        o4.x = acc[i][4] + bv; o4.y = acc[i][5] + bv;
        o4.z = acc[i][6] + bv; o4.w = acc[i][7] + bv;
        *(float4*)&g_z[b][o][n0 + tx * 8 + 4] = o4;
    }
}

// ---------------- stats of z per (b, group) ----------------
__global__ void stats3_kernel() {
    int b = blockIdx.x / NG, g = blockIdx.x % NG;
    int tid = threadIdx.x;
    float s1 = 0.f, s2 = 0.f;
    for (int i = tid; i < 32 * NPTS; i += 256) {
        int o = g * 32 + (i >> 11);
        int n = i & (NPTS - 1);
        float v = g_z[b][o][n];
        s1 += v; s2 += v * v;
    }
    __shared__ float r1[256], r2[256];
    r1[tid] = s1; r2[tid] = s2; __syncthreads();
    for (int st = 128; st; st >>= 1) {
        if (tid < st) { r1[tid] += r1[tid + st]; r2[tid] += r2[tid + st]; }
        __syncthreads();
    }
    if (tid == 0) { g_ssum[b * NG + g] = r1[0]; g_ssq[b * NG + g] = r2[0]; }
}

// ---------------- GN+lrelu+global max/mean pooling ----------------
__global__ void pool_kernel(const float* __restrict__ g3, const float* __restrict__ h3) {
    int b = blockIdx.x >> 8, o = blockIdx.x & 255;
    int g = o >> 5;
    float cnt = 32.f * NPTS;
    float mean = g_ssum[b * NG + g] / cnt;
    float var = fmaxf(g_ssq[b * NG + g] / cnt - mean * mean, 0.f);
    float inv = rsqrtf(var + EPSV);
    float s = g3[o] * inv;
    float tt = h3[o] - mean * s;
    int tid = threadIdx.x;
    float mx = NEG_INF, sum = 0.f;
    for (int n = tid; n < NPTS; n += 256) {
        float v = s * g_z[b][o][n] + tt;
        v = (v >= 0.f) ? v : 0.2f * v;
        mx = fmaxf(mx, v); sum += v;
    }
    __shared__ float rm[256], rs_[256];
    rm[tid] = mx; rs_[tid] = sum; __syncthreads();
    for (int st = 128; st; st >>= 1) {
        if (tid < st) { rm[tid] = fmaxf(rm[tid], rm[tid + st]); rs_[tid] += rs_[tid + st]; }
        __syncthreads();
    }
    if (tid == 0) { g_pool[b][o] = rm[0]; g_pool[b][256 + o] = rs_[0] / (float)NPTS; }
}

// ---------------- FC head ----------------
__global__ void head_kernel(const float* __restrict__ fw0, const float* __restrict__ fb0,
                            const float* __restrict__ fw1, const float* __restrict__ fb1,
                            const float* __restrict__ fw2, const float* __restrict__ fb2,
                            float* __restrict__ out) {
    __shared__ float sv[512];
    int b = blockIdx.x, t = threadIdx.x;
    sv[t] = g_pool[b][t];
    __syncthreads();
    float acc = fb0[t];
    {
        const float4* w4 = (const float4*)(fw0 + t * 512);
        const float4* v4 = (const float4*)sv;
        for (int c4 = 0; c4 < 128; ++c4) {
            float4 w = w4[c4]; float4 v = v4[c4];
            acc += w.x * v.x + w.y * v.y + w.z * v.z + w.w * v.w;
        }
    }
    acc = (acc >= 0.f) ? acc : 0.2f * acc;
    __syncthreads(); sv[t] = acc; __syncthreads();
    acc = fb1[t];
    {
        const float4* w4 = (const float4*)(fw1 + t * 512);
        const float4* v4 = (const float4*)sv;
        for (int c4 = 0; c4 < 128; ++c4) {
            float4 w = w4[c4]; float4 v = v4[c4];
            acc += w.x * v.x + w.y * v.y + w.z * v.z + w.w * v.w;
        }
    }
    acc = (acc >= 0.f) ? acc : 0.2f * acc;
    __syncthreads(); sv[t] = acc; __syncthreads();
    if (t < 256) {
        float a2 = fb2[t];
        const float4* w4 = (const float4*)(fw2 + t * 512);
        const float4* v4 = (const float4*)sv;
        for (int c4 = 0; c4 < 128; ++c4) {
            float4 w = w4[c4]; float4 v = v4[c4];
            a2 += w.x * v.x + w.y * v.y + w.z * v.z + w.w * v.w;
        }
        out[b * 256 + t] = a2;
    }
}

extern "C" void kernel_launch(void* const* d_in, const int* in_sizes, int n_in,
                              void* d_out, int out_size) {
    const float* x  = (const float*)d_in[0];
    const float* w0 = (const float*)d_in[1];
    const float* b0 = (const float*)d_in[2];
    const float* g0 = (const float*)d_in[3];
    const float* h0 = (const float*)d_in[4];
    const float* w1 = (const float*)d_in[5];
    const float* b1 = (const float*)d_in[6];
    const float* g1 = (const float*)d_in[7];
    const float* h1 = (const float*)d_in[8];
    const float* w2 = (const float*)d_in[9];
    const float* b2 = (const float*)d_in[10];
    const float* g2 = (const float*)d_in[11];
    const float* h2 = (const float*)d_in[12];
    const float* w3 = (const float*)d_in[13];
    const float* b3 = (const float*)d_in[14];
    const float* g3 = (const float*)d_in[15];
    const float* h3 = (const float*)d_in[16];
    const float* fw0 = (const float*)d_in[17];
    const float* fb0 = (const float*)d_in[18];
    const float* fw1 = (const float*)d_in[19];
    const float* fb1 = (const float*)d_in[20];
    const float* fw2 = (const float*)d_in[21];
    const float* fb2 = (const float*)d_in[22];
    float* out = (float*)d_out;

    float* resp = nullptr;
    cudaGetSymbolAddress((void**)&resp, g_res);

    dim3 blk16(16, 16);
    dim3 pd128grid(NPTS / 128, NPTS / 128, BB);

    // ---------- stage 1: C=3 -> O=64 ----------
    // order: xx(0), uv(1), pd(2), topk(3)  -> ncu captures launch index 3 = topk
    {
        long long bs = (long long)NPTS * 3;
        xx_kernel<<<BB * NPTS / 8, 256>>>(x, bs, 3, 3);
        uv_gemm<3><<<dim3(NPTS / 64, BB, 1), blk16>>>(x, bs, 3, w0, b0);
        pd_kernel<3><<<dim3(NPTS / 64, NPTS / 64, BB), blk16>>>(x, bs, 3);
        topk_kernel<<<BB * NPTS, 256>>>();
        gather_reduce<64, 16><<<dim3(NPTS / 16, BB), dim3(64, 4)>>>();
        apply_kernel<64><<<BB * NPTS * 64 / 256, 256>>>(g0, h0, 0);
    }
    // ---------- stage 2 ----------
    {
        long long bs = (long long)NPTS * 256;
        xx_kernel<<<BB * NPTS / 8, 256>>>(resp, bs, 256, 64);
        uv_gemm<64><<<dim3(NPTS / 64, BB, 1), blk16>>>(resp, bs, 256, w1, b1);
        pd_kernel128<<<pd128grid, blk16>>>(resp, bs, 256);
        topk_kernel<<<BB * NPTS, 256>>>();
        gather_reduce<64, 16><<<dim3(NPTS / 16, BB), dim3(64, 4)>>>();
        apply_kernel<64><<<BB * NPTS * 64 / 256, 256>>>(g1, h1, 64);
    }
    // ---------- stage 3 ----------
    {
        long long bs = (long long)NPTS * 256;
        const float* f = resp + 64;
        xx_kernel<<<BB * NPTS / 8, 256>>>(f, bs, 256, 64);
        uv_gemm<64><<<dim3(NPTS / 64, BB, 2), blk16>>>(f, bs, 256, w2, b2);
        pd_kernel128<<<pd128grid, blk16>>>(f, bs, 256);
        topk_kernel<<<BB * NPTS, 256>>>();
        gather_reduce<128, 8><<<dim3(NPTS / 8, BB), dim3(128, 2)>>>();
        apply_kernel<128><<<BB * NPTS * 128 / 256, 256>>>(g2, h2, 128);
    }
    // ---------- w3 pointwise + GN + pool + head ----------
    w3_gemm128<<<dim3(NPTS / 128, 256 / 128, BB), blk16>>>(w3, b3);
    stats3_kernel<<<BB * NG, 256>>>();
    pool_kernel<<<BB * 256, 256>>>(g3, h3);
    head_kernel<<<BB, 512>>>(fw0, fb0, fw1, fb1, fw2, fb2, out);
}

// round 17
// speedup vs baseline: 1.0377x; 1.0009x over previous
#include <cuda_runtime.h>

#define BB 8
#define NPTS 2048
#define KNN 20
#define NG 8
#define EPSV 1e-5f

#define NEG_INF __int_as_float(0xff800000)
#define POS_INF __int_as_float(0x7f800000)

// ---------------- device scratch ----------------
__device__ float g_pd[BB][NPTS][NPTS];
__device__ float g_xx[BB][NPTS];
__device__ int   g_knn[BB][NPTS][KNN];
__device__ float g_res[BB][NPTS][256];
__device__ float g_U[BB][NPTS][128];
__device__ float g_V[BB][NPTS][128];
__device__ float g_maxv[BB][NPTS][128];
__device__ float g_minv[BB][NPTS][128];
__device__ float g_z[BB][256][NPTS];
__device__ float g_ssum[BB * NG];
__device__ float g_ssq[BB * NG];
__device__ float g_pool[BB][512];

// ---------------- xx = sum_c f^2 (+ zero the stage stats) ----------------
__global__ void xx_kernel(const float* __restrict__ f, long long bs, int rs, int C) {
    if (blockIdx.x == 0 && threadIdx.x < BB * NG) {
        g_ssum[threadIdx.x] = 0.f; g_ssq[threadIdx.x] = 0.f;
    }
    int row = blockIdx.x * 8 + (threadIdx.x >> 5);
    int lane = threadIdx.x & 31;
    int b = row / NPTS, n = row % NPTS;
    const float* p = f + (long long)b * bs + (long long)n * rs;
    float s = 0.f;
    for (int c = lane; c < C; c += 32) { float v = p[c]; s += v * v; }
#pragma unroll
    for (int o = 16; o; o >>= 1) s += __shfl_xor_sync(0xffffffffu, s, o);
    if (lane == 0) g_xx[b][n] = s;
}

// ---------------- pd (C=3 path): 64x64 tile ----------------
template <int C>
__global__ void pd_kernel(const float* __restrict__ f, long long bs, int rs) {
    constexpr int KT = (C < 32) ? C : 32;
    __shared__ float sA[KT][68];
    __shared__ float sB[KT][68];
    int b = blockIdx.z;
    int n0 = blockIdx.y * 64, m0 = blockIdx.x * 64;
    int tx = threadIdx.x, ty = threadIdx.y;
    int tid = ty * 16 + tx;
    const float* fb = f + (long long)b * bs;
    float acc[4][4];
#pragma unroll
    for (int i = 0; i < 4; ++i)
#pragma unroll
        for (int j = 0; j < 4; ++j) acc[i][j] = 0.f;

    for (int k0 = 0; k0 < C; k0 += KT) {
        for (int t = tid; t < 64 * KT; t += 256) {
            int r = t / KT, c = t - r * KT;
            sA[c][r] = fb[(long long)(n0 + r) * rs + k0 + c];
            sB[c][r] = fb[(long long)(m0 + r) * rs + k0 + c];
        }
        __syncthreads();
#pragma unroll
        for (int c = 0; c < KT; ++c) {
            float4 a4 = *(const float4*)&sA[c][ty * 4];
            float4 b4 = *(const float4*)&sB[c][tx * 4];
            float a[4] = {a4.x, a4.y, a4.z, a4.w};
            float bv[4] = {b4.x, b4.y, b4.z, b4.w};
#pragma unroll
            for (int i = 0; i < 4; ++i)
#pragma unroll
                for (int j = 0; j < 4; ++j) acc[i][j] += a[i] * bv[j];
        }
        __syncthreads();
    }
    float xn[4], xm[4];
#pragma unroll
    for (int i = 0; i < 4; ++i) xn[i] = g_xx[b][n0 + ty * 4 + i];
#pragma unroll
    for (int j = 0; j < 4; ++j) xm[j] = g_xx[b][m0 + tx * 4 + j];
#pragma unroll
    for (int i = 0; i < 4; ++i) {
        float4 o4;
        o4.x = -(xn[i] - 2.f * acc[i][0] + xm[0]);
        o4.y = -(xn[i] - 2.f * acc[i][1] + xm[1]);
        o4.z = -(xn[i] - 2.f * acc[i][2] + xm[2]);
        o4.w = -(xn[i] - 2.f * acc[i][3] + xm[3]);
        __stcs((float4*)&g_pd[b][n0 + ty * 4 + i][m0 + tx * 4], o4);
    }
}

// ---------------- pd (C=64 path): 128x128 tile, 8x8 per thread ----------------
__global__ void __launch_bounds__(256) pd_kernel128(const float* __restrict__ f, long long bs, int rs) {
    __shared__ float sA[32][132];
    __shared__ float sB[32][132];
    int b = blockIdx.z;
    int n0 = blockIdx.y * 128, m0 = blockIdx.x * 128;
    int tx = threadIdx.x, ty = threadIdx.y;
    int tid = ty * 16 + tx;
    const float* fb = f + (long long)b * bs;
    float acc[8][8];
#pragma unroll
    for (int i = 0; i < 8; ++i)
#pragma unroll
        for (int j = 0; j < 8; ++j) acc[i][j] = 0.f;

    for (int k0 = 0; k0 < 64; k0 += 32) {
        for (int t = tid; t < 128 * 32; t += 256) {
            int r = t >> 5, c = t & 31;
            sA[c][r] = fb[(long long)(n0 + r) * rs + k0 + c];
            sB[c][r] = fb[(long long)(m0 + r) * rs + k0 + c];
        }
        __syncthreads();
#pragma unroll
        for (int c = 0; c < 32; ++c) {
            float4 a0 = *(const float4*)&sA[c][ty * 8];
            float4 a1 = *(const float4*)&sA[c][ty * 8 + 4];
            float4 b0 = *(const float4*)&sB[c][tx * 8];
            float4 b1 = *(const float4*)&sB[c][tx * 8 + 4];
            float a[8] = {a0.x, a0.y, a0.z, a0.w, a1.x, a1.y, a1.z, a1.w};
            float bv[8] = {b0.x, b0.y, b0.z, b0.w, b1.x, b1.y, b1.z, b1.w};
#pragma unroll
            for (int i = 0; i < 8; ++i)
#pragma unroll
                for (int j = 0; j < 8; ++j) acc[i][j] += a[i] * bv[j];
        }
        __syncthreads();
    }
    float xn[8], xm[8];
#pragma unroll
    for (int i = 0; i < 8; ++i) xn[i] = g_xx[b][n0 + ty * 8 + i];
#pragma unroll
    for (int j = 0; j < 8; ++j) xm[j] = g_xx[b][m0 + tx * 8 + j];
#pragma unroll
    for (int i = 0; i < 8; ++i) {
        int n = n0 + ty * 8 + i;
        float4 o4;
        o4.x = -(xn[i] - 2.f * acc[i][0] + xm[0]);
        o4.y = -(xn[i] - 2.f * acc[i][1] + xm[1]);
        o4.z = -(xn[i] - 2.f * acc[i][2] + xm[2]);
        o4.w = -(xn[i] - 2.f * acc[i][3] + xm[3]);
        __stcs((float4*)&g_pd[b][n][m0 + tx * 8], o4);
        o4.x = -(xn[i] - 2.f * acc[i][4] + xm[4]);
        o4.y = -(xn[i] - 2.f * acc[i][5] + xm[5]);
        o4.z = -(xn[i] - 2.f * acc[i][6] + xm[6]);
        o4.w = -(xn[i] - 2.f * acc[i][7] + xm[7]);
        __stcs((float4*)&g_pd[b][n][m0 + tx * 8 + 4], o4);
    }
}

// ---------------- exact top-K per row: rank-20 threshold + distributed rank pass ----------------
__device__ __forceinline__ unsigned int fkey(float x) {
    unsigned int u = __float_as_uint(x);
    return (u & 0x80000000u) ? ~u : (u | 0x80000000u);
}

#define FASTCAP 512

__global__ void __launch_bounds__(256) topk_kernel() {
    __shared__ unsigned long long skey[FASTCAP];
    __shared__ int srank[FASTCAP];
    __shared__ float sgmax[32];
    __shared__ float sT;
    __shared__ int s_cand;

    int row = blockIdx.x;
    int b = row >> 11, n = row & (NPTS - 1);
    int tid = threadIdx.x;
    int w = tid >> 5, lane = tid & 31;

    if (tid == 0) s_cand = 0;
    // pre-zero rank array (used by the fast path) to save a barrier later
    srank[tid] = 0; srank[tid + 256] = 0;

    // load 8 contiguous elements per thread, keep in registers
    const float4* pr4 = (const float4*)&g_pd[b][n][0];
    float4 x0 = __ldcs(&pr4[tid * 2]);
    float4 x1 = __ldcs(&pr4[tid * 2 + 1]);
    float xv[8] = {x0.x, x0.y, x0.z, x0.w, x1.x, x1.y, x1.z, x1.w};

    // ---- per-thread max, then 32 disjoint group maxima (8 lanes = 64 elems each) ----
    float tmax = xv[0];
#pragma unroll
    for (int q = 1; q < 8; ++q) tmax = fmaxf(tmax, xv[q]);
    float lm = tmax;
#pragma unroll
    for (int o = 1; o < 8; o <<= 1) lm = fmaxf(lm, __shfl_xor_sync(0xffffffffu, lm, o));
    if ((lane & 7) == 0) sgmax[w * 4 + (lane >> 3)] = lm;
    __syncthreads();

    // ---- T = 20th largest of the 32 group maxima (unique (value, lane) order) ----
    // The 20 top maxima are DISTINCT elements >= T  =>  survivors >= KNN guaranteed.
    if (tid < 32) {
        float v = sgmax[tid];
        int cnt = 0;
#pragma unroll
        for (int j = 0; j < 32; ++j) {
            float vj = __shfl_sync(0xffffffffu, v, j);
            cnt += (vj > v) || (vj == v && j < tid);
        }
        if (cnt == KNN - 1) sT = v;
    }
    __syncthreads();
    float T = sT;

    // ---- compact survivors (x >= T) as packed u64 keys: (fkey << 32) | ~idx ----
    if (tmax >= T) {
        unsigned int ibase = 0xffffffffu - (unsigned int)(tid * 8);
#pragma unroll
        for (int q = 0; q < 8; ++q) {
            if (xv[q] >= T) {
                int pos = atomicAdd(&s_cand, 1);
                if (pos < FASTCAP)
                    skey[pos] = ((unsigned long long)fkey(xv[q]) << 32) | (ibase - q);
            }
        }
    }
    __syncthreads();
    int c = s_cand;

    if (c <= FASTCAP) {
        // ---- distributed parallel rank pass: keys unique; exactly KNN ranks < KNN ----
        if (c <= 128) {
            int nch = 256 / c;
            if (tid < nch * c) {
                int p = tid % c, ch = tid / c;
                unsigned long long mk = skey[p];
                int cnt = 0;
                for (int i = ch; i < c; i += nch) cnt += (skey[i] > mk);
                if (cnt) atomicAdd(&srank[p], cnt);
            }
        } else {
            for (int p = tid; p < c; p += 256) {
                unsigned long long mk = skey[p];
                int cnt = 0;
                for (int i = 0; i < c; ++i) cnt += (skey[i] > mk);
                srank[p] = cnt;
            }
        }
        __syncthreads();
        for (int p = tid; p < c; p += 256) {
            int r = srank[p];
            if (r < KNN)
                g_knn[b][n][r] = (int)(0xffffffffu - (unsigned int)(skey[p] & 0xffffffffu));
        }
        return;
    }

    // ---- fallback (massive tie storms only; never taken in practice): ----
    // 20-round block argmax over the register-resident elements. Exact
    // (value desc, index asc) order via unique packed keys. Uses only skey.
    __syncthreads();
    unsigned int emitted = 0;
    unsigned int ibase = 0xffffffffu - (unsigned int)(tid * 8);
    for (int round = 0; round < KNN; ++round) {
        unsigned long long best = 0ull;
#pragma unroll
        for (int q = 0; q < 8; ++q) {
            if (!((emitted >> q) & 1u)) {
                unsigned long long pk = ((unsigned long long)fkey(xv[q]) << 32) | (ibase - q);
                if (pk > best) best = pk;
            }
        }
        skey[tid] = best;
        __syncthreads();
        for (int st = 128; st; st >>= 1) {
            if (tid < st) {
                unsigned long long o = skey[tid + st];
                if (o > skey[tid]) skey[tid] = o;
            }
            __syncthreads();
        }
        unsigned long long wb = skey[0];
        __syncthreads();
#pragma unroll
        for (int q = 0; q < 8; ++q) {
            if (!((emitted >> q) & 1u)) {
                unsigned long long pk = ((unsigned long long)fkey(xv[q]) << 32) | (ibase - q);
                if (pk == wb) emitted |= (1u << q);
            }
        }
        if (tid == 0)
            g_knn[b][n][round] = (int)(0xffffffffu - (unsigned int)(wb & 0xffffffffu));
    }
}

// ---------------- U = f*W1^T, V = f*(W2-W1)^T + b ----------------
template <int C>
__global__ void uv_gemm(const float* __restrict__ f, long long bs, int rs,
                        const float* __restrict__ w, const float* __restrict__ bias) {
    constexpr int KT = (C < 32) ? C : 32;
    __shared__ float sF[KT][68];
    __shared__ float sW1[KT][68];
    __shared__ float sDW[KT][68];
    int b = blockIdx.y;
    int n0 = blockIdx.x * 64;
    int o0 = blockIdx.z * 64;
    int tx = threadIdx.x, ty = threadIdx.y;
    int tid = ty * 16 + tx;
    const float* fb = f + (long long)b * bs;
    float au[4][4], av[4][4];
#pragma unroll
    for (int i = 0; i < 4; ++i)
#pragma unroll
        for (int j = 0; j < 4; ++j) { au[i][j] = 0.f; av[i][j] = 0.f; }

    for (int k0 = 0; k0 < C; k0 += KT) {
        for (int t = tid; t < 64 * KT; t += 256) {
            int r = t / KT, c = t - r * KT;
            sF[c][r] = fb[(long long)(n0 + r) * rs + k0 + c];
            float w1 = w[(o0 + r) * 2 * C + k0 + c];
            float w2 = w[(o0 + r) * 2 * C + C + k0 + c];
            sW1[c][r] = w1; sDW[c][r] = w2 - w1;
        }
        __syncthreads();
#pragma unroll
        for (int c = 0; c < KT; ++c) {
            float4 f4 = *(const float4*)&sF[c][ty * 4];
            float4 w4 = *(const float4*)&sW1[c][tx * 4];
            float4 d4 = *(const float4*)&sDW[c][tx * 4];
            float a[4] = {f4.x, f4.y, f4.z, f4.w};
            float wv[4] = {w4.x, w4.y, w4.z, w4.w};
            float dv[4] = {d4.x, d4.y, d4.z, d4.w};
#pragma unroll
            for (int i = 0; i < 4; ++i)
#pragma unroll
                for (int j = 0; j < 4; ++j) {
                    au[i][j] += a[i] * wv[j];
                    av[i][j] += a[i] * dv[j];
                }
        }
        __syncthreads();
    }
    float bb0 = bias[o0 + tx * 4 + 0];
    float bb1 = bias[o0 + tx * 4 + 1];
    float bb2 = bias[o0 + tx * 4 + 2];
    float bb3 = bias[o0 + tx * 4 + 3];
#pragma unroll
    for (int i = 0; i < 4; ++i) {
        int n = n0 + ty * 4 + i;
        float4 u4 = {au[i][0], au[i][1], au[i][2], au[i][3]};
        float4 v4 = {av[i][0] + bb0, av[i][1] + bb1, av[i][2] + bb2, av[i][3] + bb3};
        *(float4*)&g_U[b][n][o0 + tx * 4] = u4;
        *(float4*)&g_V[b][n][o0 + tx * 4] = v4;
    }
}

// ---------------- gather + k-max/min + GN stats ----------------
template <int O, int P>
__global__ void gather_reduce() {
    constexpr int PY = 256 / O;
    __shared__ int sidx[P][KNN];
    __shared__ float red[256];
    int o = threadIdx.x, py = threadIdx.y;
    int t = py * O + o;
    int b = blockIdx.y, n0 = blockIdx.x * P;
    for (int j = t; j < P * KNN; j += 256)
        sidx[j / KNN][j % KNN] = g_knn[b][n0 + j / KNN][j % KNN];
    __syncthreads();
    float ts1 = 0.f, ts2 = 0.f;
    for (int p = py; p < P; p += PY) {
        int n = n0 + p;
        float v = g_V[b][n][o];
        float mx = NEG_INF, mn = POS_INF;
#pragma unroll
        for (int k = 0; k < KNN; ++k) {
            float y = g_U[b][sidx[p][k]][o] + v;
            mx = fmaxf(mx, y); mn = fminf(mn, y);
            ts1 += y; ts2 += y * y;
        }
        g_maxv[b][n][o] = mx;
        g_minv[b][n][o] = mn;
    }
    red[t] = ts1; __syncthreads();
    if (t < NG) {
        float s = 0.f;
        for (int pp = 0; pp < PY; ++pp)
            for (int i = 0; i < O / NG; ++i) s += red[pp * O + t * (O / NG) + i];
        atomicAdd(&g_ssum[b * NG + t], s);
    }
    __syncthreads();
    red[t] = ts2; __syncthreads();
    if (t < NG) {
        float s = 0.f;
        for (int pp = 0; pp < PY; ++pp)
            for (int i = 0; i < O / NG; ++i) s += red[pp * O + t * (O / NG) + i];
        atomicAdd(&g_ssq[b * NG + t], s);
    }
}

// ---------------- GN + lrelu applied to k-extremum ----------------
template <int O>
__global__ void apply_kernel(const float* __restrict__ gamma, const float* __restrict__ beta, int col0) {
    int l = blockIdx.x * blockDim.x + threadIdx.x;
    int o = l % O;
    int n = (l / O) % NPTS;
    int b = l / (O * NPTS);
    int g = o / (O / NG);
    float cnt = (float)(O / NG) * NPTS * KNN;
    float mean = g_ssum[b * NG + g] / cnt;
    float var = fmaxf(g_ssq[b * NG + g] / cnt - mean * mean, 0.f);
    float inv = rsqrtf(var + EPSV);
    float s = gamma[o] * inv;
    float tt = beta[o] - mean * s;
    float sel = (s >= 0.f) ? g_maxv[b][n][o] : g_minv[b][n][o];
    float yv = s * sel + tt;
    g_res[b][n][col0 + o] = (yv >= 0.f) ? yv : 0.2f * yv;
}

// ---------------- w3 pointwise GEMM: 128x128 tile, 8x8 per thread ----------------
__global__ void __launch_bounds__(256) w3_gemm128(const float* __restrict__ w3, const float* __restrict__ b3) {
    __shared__ float sW[32][132];
    __shared__ float sR[32][132];
    int b = blockIdx.z;
    int o0 = blockIdx.y * 128, n0 = blockIdx.x * 128;
    int tx = threadIdx.x, ty = threadIdx.y;
    int tid = ty * 16 + tx;
    float acc[8][8];
#pragma unroll
    for (int i = 0; i < 8; ++i)
#pragma unroll
        for (int j = 0; j < 8; ++j) acc[i][j] = 0.f;

    for (int k0 = 0; k0 < 256; k0 += 32) {
        for (int t = tid; t < 128 * 32; t += 256) {
            int r = t >> 5, c = t & 31;
            sW[c][r] = w3[(o0 + r) * 256 + k0 + c];
            sR[c][r] = g_res[b][n0 + r][k0 + c];
        }
        __syncthreads();
#pragma unroll
        for (int c = 0; c < 32; ++c) {
            float4 a0 = *(const float4*)&sW[c][ty * 8];
            float4 a1 = *(const float4*)&sW[c][ty * 8 + 4];
            float4 b0 = *(const float4*)&sR[c][tx * 8];
            float4 b1 = *(const float4*)&sR[c][tx * 8 + 4];
            float a[8] = {a0.x, a0.y, a0.z, a0.w, a1.x, a1.y, a1.z, a1.w};
            float bv[8] = {b0.x, b0.y, b0.z, b0.w, b1.x, b1.y, b1.z, b1.w};
#pragma unroll
            for (int i = 0; i < 8; ++i)
#pragma unroll
                for (int j = 0; j < 8; ++j) acc[i][j] += a[i] * bv[j];
        }
        __syncthreads();
    }
#pragma unroll
    for (int i = 0; i < 8; ++i) {
        int o = o0 + ty * 8 + i;
        float bv = b3[o];
        float4 o4;
        o4.x = acc[i][0] + bv; o4.y = acc[i][1] + bv;
        o4.z = acc[i][2] + bv; o4.w = acc[i][3] + bv;
        *(float4*)&g_z[b][o][n0 + tx * 8] = o4;
        o4.x = acc[i][4] + bv; o4.y = acc[i][5] + bv;
        o4.z = acc[i][6] + bv; o4.w = acc[i][7] + bv;
        *(float4*)&g_z[b][o][n0 + tx * 8 + 4] = o4;
    }
}

// ---------------- stats of z per (b, group) ----------------
__global__ void stats3_kernel() {
    int b = blockIdx.x / NG, g = blockIdx.x % NG;
    int tid = threadIdx.x;
    float s1 = 0.f, s2 = 0.f;
    for (int i = tid; i < 32 * NPTS; i += 256) {
        int o = g * 32 + (i >> 11);
        int n = i & (NPTS - 1);
        float v = g_z[b][o][n];
        s1 += v; s2 += v * v;
    }
    __shared__ float r1[256], r2[256];
    r1[tid] = s1; r2[tid] = s2; __syncthreads();
    for (int st = 128; st; st >>= 1) {
        if (tid < st) { r1[tid] += r1[tid + st]; r2[tid] += r2[tid + st]; }
        __syncthreads();
    }
    if (tid == 0) { g_ssum[b * NG + g] = r1[0]; g_ssq[b * NG + g] = r2[0]; }
}

// ---------------- GN+lrelu+global max/mean pooling ----------------
__global__ void pool_kernel(const float* __restrict__ g3, const float* __restrict__ h3) {
    int b = blockIdx.x >> 8, o = blockIdx.x & 255;
    int g = o >> 5;
    float cnt = 32.f * NPTS;
    float mean = g_ssum[b * NG + g] / cnt;
    float var = fmaxf(g_ssq[b * NG + g] / cnt - mean * mean, 0.f);
    float inv = rsqrtf(var + EPSV);
    float s = g3[o] * inv;
    float tt = h3[o] - mean * s;
    int tid = threadIdx.x;
    float mx = NEG_INF, sum = 0.f;
    for (int n = tid; n < NPTS; n += 256) {
        float v = s * g_z[b][o][n] + tt;
        v = (v >= 0.f) ? v : 0.2f * v;
        mx = fmaxf(mx, v); sum += v;
    }
    __shared__ float rm[256], rs_[256];
    rm[tid] = mx; rs_[tid] = sum; __syncthreads();
    for (int st = 128; st; st >>= 1) {
        if (tid < st) { rm[tid] = fmaxf(rm[tid], rm[tid + st]); rs_[tid] += rs_[tid + st]; }
        __syncthreads();
    }
    if (tid == 0) { g_pool[b][o] = rm[0]; g_pool[b][256 + o] = rs_[0] / (float)NPTS; }
}

// ---------------- FC head ----------------
__global__ void head_kernel(const float* __restrict__ fw0, const float* __restrict__ fb0,
                            const float* __restrict__ fw1, const float* __restrict__ fb1,
                            const float* __restrict__ fw2, const float* __restrict__ fb2,
                            float* __restrict__ out) {
    __shared__ float sv[512];
    int b = blockIdx.x, t = threadIdx.x;
    sv[t] = g_pool[b][t];
    __syncthreads();
    float acc = fb0[t];
    {
        const float4* w4 = (const float4*)(fw0 + t * 512);
        const float4* v4 = (const float4*)sv;
        for (int c4 = 0; c4 < 128; ++c4) {
            float4 w = w4[c4]; float4 v = v4[c4];
            acc += w.x * v.x + w.y * v.y + w.z * v.z + w.w * v.w;
        }
    }
    acc = (acc >= 0.f) ? acc : 0.2f * acc;
    __syncthreads(); sv[t] = acc; __syncthreads();
    acc = fb1[t];
    {
        const float4* w4 = (const float4*)(fw1 + t * 512);
        const float4* v4 = (const float4*)sv;
        for (int c4 = 0; c4 < 128; ++c4) {
            float4 w = w4[c4]; float4 v = v4[c4];
            acc += w.x * v.x + w.y * v.y + w.z * v.z + w.w * v.w;
        }
    }
    acc = (acc >= 0.f) ? acc : 0.2f * acc;
    __syncthreads(); sv[t] = acc; __syncthreads();
    if (t < 256) {
        float a2 = fb2[t];
        const float4* w4 = (const float4*)(fw2 + t * 512);
        const float4* v4 = (const float4*)sv;
        for (int c4 = 0; c4 < 128; ++c4) {
            float4 w = w4[c4]; float4 v = v4[c4];
            a2 += w.x * v.x + w.y * v.y + w.z * v.z + w.w * v.w;
        }
        out[b * 256 + t] = a2;
    }
}

extern "C" void kernel_launch(void* const* d_in, const int* in_sizes, int n_in,
                              void* d_out, int out_size) {
    const float* x  = (const float*)d_in[0];
    const float* w0 = (const float*)d_in[1];
    const float* b0 = (const float*)d_in[2];
    const float* g0 = (const float*)d_in[3];
    const float* h0 = (const float*)d_in[4];
    const float* w1 = (const float*)d_in[5];
    const float* b1 = (const float*)d_in[6];
    const float* g1 = (const float*)d_in[7];
    const float* h1 = (const float*)d_in[8];
    const float* w2 = (const float*)d_in[9];
    const float* b2 = (const float*)d_in[10];
    const float* g2 = (const float*)d_in[11];
    const float* h2 = (const float*)d_in[12];
    const float* w3 = (const float*)d_in[13];
    const float* b3 = (const float*)d_in[14];
    const float* g3 = (const float*)d_in[15];
    const float* h3 = (const float*)d_in[16];
    const float* fw0 = (const float*)d_in[17];
    const float* fb0 = (const float*)d_in[18];
    const float* fw1 = (const float*)d_in[19];
    const float* fb1 = (const float*)d_in[20];
    const float* fw2 = (const float*)d_in[21];
    const float* fb2 = (const float*)d_in[22];
    float* out = (float*)d_out;

    float* resp = nullptr;
    cudaGetSymbolAddress((void**)&resp, g_res);

    dim3 blk16(16, 16);
    dim3 pd128grid(NPTS / 128, NPTS / 128, BB);

    // ---------- stage 1: C=3 -> O=64 ----------
    // order: xx(0), uv(1), pd(2), topk(3)  -> ncu captures launch index 3 = topk
    {
        long long bs = (long long)NPTS * 3;
        xx_kernel<<<BB * NPTS / 8, 256>>>(x, bs, 3, 3);
        uv_gemm<3><<<dim3(NPTS / 64, BB, 1), blk16>>>(x, bs, 3, w0, b0);
        pd_kernel<3><<<dim3(NPTS / 64, NPTS / 64, BB), blk16>>>(x, bs, 3);
        topk_kernel<<<BB * NPTS, 256>>>();
        gather_reduce<64, 16><<<dim3(NPTS / 16, BB), dim3(64, 4)>>>();
        apply_kernel<64><<<BB * NPTS * 64 / 256, 256>>>(g0, h0, 0);
    }
    // ---------- stage 2 ----------
    {
        long long bs = (long long)NPTS * 256;
        xx_kernel<<<BB * NPTS / 8, 256>>>(resp, bs, 256, 64);
        uv_gemm<64><<<dim3(NPTS / 64, BB, 1), blk16>>>(resp, bs, 256, w1, b1);
        pd_kernel128<<<pd128grid, blk16>>>(resp, bs, 256);
        topk_kernel<<<BB * NPTS, 256>>>();
        gather_reduce<64, 16><<<dim3(NPTS / 16, BB), dim3(64, 4)>>>();
        apply_kernel<64><<<BB * NPTS * 64 / 256, 256>>>(g1, h1, 64);
    }
    // ---------- stage 3 ----------
    {
        long long bs = (long long)NPTS * 256;
        const float* f = resp + 64;
        xx_kernel<<<BB * NPTS / 8, 256>>>(f, bs, 256, 64);
        uv_gemm<64><<<dim3(NPTS / 64, BB, 2), blk16>>>(f, bs, 256, w2, b2);
        pd_kernel128<<<pd128grid, blk16>>>(f, bs, 256);
        topk_kernel<<<BB * NPTS, 256>>>();
        gather_reduce<128, 8><<<dim3(NPTS / 8, BB), dim3(128, 2)>>>();
        apply_kernel<128><<<BB * NPTS * 128 / 256, 256>>>(g2, h2, 128);
    }
    // ---------- w3 pointwise + GN + pool + head ----------
    w3_gemm128<<<dim3(NPTS / 128, 256 / 128, BB), blk16>>>(w3, b3);
    stats3_kernel<<<BB * NG, 256>>>();
    pool_kernel<<<BB * 256, 256>>>(g3, h3);
    head_kernel<<<BB, 512>>>(fw0, fb0, fw1, fb1, fw2, fb2, out);
}